// round 15
// baseline (speedup 1.0000x reference)
#include <cuda_runtime.h>
#include <math.h>

#define FULL 0xffffffffu
typedef unsigned long long u64;

// Scratch token buffer: (B=16, T=128, slots=67, EMBED=32) fp32
__device__ float g_tokens[16 * 128 * 67 * 32];

__device__ __forceinline__ float warp_sum(float v) {
    v += __shfl_xor_sync(FULL, v, 16);
    v += __shfl_xor_sync(FULL, v, 8);
    v += __shfl_xor_sync(FULL, v, 4);
    v += __shfl_xor_sync(FULL, v, 2);
    v += __shfl_xor_sync(FULL, v, 1);
    return v;
}

// ---- packed f32x2 helpers ----
__device__ __forceinline__ u64 fma2(u64 a, u64 b, u64 c) {
    u64 d; asm("fma.rn.f32x2 %0, %1, %2, %3;" : "=l"(d) : "l"(a), "l"(b), "l"(c)); return d;
}
__device__ __forceinline__ u64 mul2(u64 a, u64 b) {
    u64 d; asm("mul.rn.f32x2 %0, %1, %2;" : "=l"(d) : "l"(a), "l"(b)); return d;
}
__device__ __forceinline__ u64 add2(u64 a, u64 b) {
    u64 d; asm("add.rn.f32x2 %0, %1, %2;" : "=l"(d) : "l"(a), "l"(b)); return d;
}
__device__ __forceinline__ u64 pack2(float lo, float hi) {
    u64 d; asm("mov.b64 %0, {%1, %2};" : "=l"(d) : "f"(lo), "f"(hi)); return d;
}
__device__ __forceinline__ float hsum2(u64 v) {
    float lo, hi; asm("mov.b64 {%0, %1}, %2;" : "=f"(lo), "=f"(hi) : "l"(v)); return lo + hi;
}
__device__ __forceinline__ void unpk(u64 v, float& a, float& b) {
    asm("mov.b64 {%0, %1}, %2;" : "=f"(a), "=f"(b) : "l"(v));
}
// base-2 exp, scores pre-scaled by log2(e)
__device__ __forceinline__ float ex2f(float x) {
    float y; asm("ex2.approx.f32 %0, %1;" : "=f"(y) : "f"(x)); return y;
}

__device__ __forceinline__ void ld_row16(u64* r, const float* p) {
    const ulonglong2* q = (const ulonglong2*)p;
#pragma unroll
    for (int i = 0; i < 8; i++) { ulonglong2 t = q[i]; r[2 * i] = t.x; r[2 * i + 1] = t.y; }
}

// one weight row read, TWO dots (token pair)
__device__ __forceinline__ float2 dot32x2(const float* wrow, const u64* a, const u64* b) {
    const ulonglong2* w = (const ulonglong2*)wrow;
    ulonglong2 t0 = w[0], t1 = w[1];
    u64 a0 = mul2(a[0], t0.x), b0 = mul2(b[0], t0.x);
    a0 = fma2(a[1], t0.y, a0); b0 = fma2(b[1], t0.y, b0);
    u64 a1 = mul2(a[2], t1.x), b1 = mul2(b[2], t1.x);
    a1 = fma2(a[3], t1.y, a1); b1 = fma2(b[3], t1.y, b1);
#pragma unroll
    for (int i = 2; i < 8; i += 2) {
        ulonglong2 u0 = w[i], u1 = w[i + 1];
        a0 = fma2(a[2 * i], u0.x, a0);     b0 = fma2(b[2 * i], u0.x, b0);
        a0 = fma2(a[2 * i + 1], u0.y, a0); b0 = fma2(b[2 * i + 1], u0.y, b0);
        a1 = fma2(a[2 * i + 2], u1.x, a1); b1 = fma2(b[2 * i + 2], u1.x, b1);
        a1 = fma2(a[2 * i + 3], u1.y, a1); b1 = fma2(b[2 * i + 3], u1.y, b1);
    }
    return make_float2(hsum2(add2(a0, a1)), hsum2(add2(b0, b1)));
}

__device__ __forceinline__ float sumsq16(const u64* v) {
    u64 a0 = mul2(v[0], v[0]);
    u64 a1 = mul2(v[1], v[1]);
#pragma unroll
    for (int i = 2; i < 16; i += 2) {
        a0 = fma2(v[i], v[i], a0);
        a1 = fma2(v[i + 1], v[i + 1], a1);
    }
    return hsum2(add2(a0, a1));
}

// ---------------------------------------------------------------------------
// Monolithic fused block. Transposed-K packed-score attention; 2 tokens/lane;
// head-split passes; base-2 softmax. Late FFN-weight staging in dead K^T.
// EMB0: layer-0 spatial also computes the token embedding + input rmsnorm
// in-kernel (fuses the embed kernel) and writes x to g_tokens for phase D.
// ---------------------------------------------------------------------------
template <int S, int NSEQ, bool TEMPORAL, bool EMB0>
__global__ void __launch_bounds__(32 * ((((S + 1) / 2) * NSEQ + 31) / 32))
attn_tpl(const float* __restrict__ Wq, const float* __restrict__ Wk,
         const float* __restrict__ Wv, const float* __restrict__ Wo,
         const float* __restrict__ Wg, const float* __restrict__ Wu,
         const float* __restrict__ Wout, const float* __restrict__ norm4,
         const float* __restrict__ qkn, int nseq_total,
         const float* __restrict__ eobs, const float* __restrict__ eWval,
         const float* __restrict__ ebval, const float* __restrict__ einnorm,
         const float* __restrict__ edimemb, const float* __restrict__ ecls) {
    constexpr int HS = (S + 1) / 2;
    constexpr int BLK = 32 * ((HS * NSEQ + 31) / 32);
    constexpr int SP4 = ((S + 3) / 4) * 4;       // keys padded to mult of 4
    constexpr int PADK = SP4 - S;
    constexpr int ROW = 36;
    constexpr int KTSZ = 32 * SP4;
    constexpr int VSZ = SP4 * ROW;
    constexpr int DATSZ = NSEQ * (KTSZ + VSZ);

    extern __shared__ float sm[];
    float* skT   = sm;                       // NSEQ*KTSZ (late: FFN weights)
    float* sV    = skT + NSEQ * KTSZ;        // NSEQ*VSZ
    float* swq   = sm + DATSZ;               // 1024 each
    float* swk   = swq + 1024;
    float* swv   = swk + 1024;
    float* swo   = swv + 1024;
    float* snorm = swo + 1024;               // 128
    float* sqkn  = snorm + 128;              // 16
    float* semb  = sqkn + 16;                // 192 (Wval,bval,innorm,cls)
    // late-staged FFN weights overlay the K^T block after attention:
    float* swg2   = skT;                     // 2048
    float* swu2   = skT + 2048;              // 2048
    float* swout2 = skT + 4096;              // 2048 transposed [f][d]

    const int tid = threadIdx.x;
    int gseq0 = blockIdx.x * NSEQ;

    // ---- stage QKV/Wo weights + norms ----
    for (int i = tid; i < 256; i += BLK) {
        ((float4*)swq)[i] = ((const float4*)Wq)[i];
        ((float4*)swk)[i] = ((const float4*)Wk)[i];
        ((float4*)swv)[i] = ((const float4*)Wv)[i];
        ((float4*)swo)[i] = ((const float4*)Wo)[i];
    }
    if (tid < 128) snorm[tid] = norm4[tid];
    if (tid < 16) sqkn[tid] = qkn[tid];
    if (EMB0) {
        if (tid < 32) {
            semb[tid] = eWval[tid];
            semb[32 + tid] = ebval[tid];
            semb[64 + tid] = einnorm[tid];
        }
        if (tid < 96) semb[96 + tid] = ecls[tid];
    }

    // ---- zero pad: K^T cols S..SP4-1 + V rows S..SP4-1 ----
    if (PADK > 0) {
        constexpr int PER = (32 + ROW) * PADK;
        for (int i = tid; i < NSEQ * PER; i += BLK) {
            int sq = i / PER;
            int r = i - sq * PER;
            if (r < 32 * PADK) {
                int d = r / PADK, pc = r - d * PADK;
                skT[sq * KTSZ + d * SP4 + S + pc] = 0.f;
            } else {
                int rr = r - 32 * PADK;
                sV[sq * VSZ + S * ROW + rr] = 0.f;
            }
        }
    }

    // ---- token-pair assignment ----
    int seq = tid / HS;
    int l = tid - seq * HS;
    bool seqok = (seq < NSEQ) && (gseq0 + seq < nseq_total);
    int seqc = seqok ? seq : 0;
    bool vA = seqok;
    bool vB = seqok && (l + HS < S);
    int tokA = l;
    int tokB = vB ? (l + HS) : (S - 1);

    float* kT = skT + seqc * KTSZ;
    float* vb = sV + seqc * VSZ;

    float *gxA, *gxB;
    {
        int gs = gseq0 + seqc;
        if (TEMPORAL) {
            int b = gs / 67, sl = gs - b * 67;
            gxA = g_tokens + ((long)(b * 128 + tokA) * 67 + sl) * 32;
            gxB = g_tokens + ((long)(b * 128 + tokB) * 67 + sl) * 32;
        } else {
            gxA = g_tokens + ((long)gs * 67 + tokA) * 32;
            gxB = g_tokens + ((long)gs * 67 + tokB) * 32;
        }
    }

    __syncthreads();

    u64 qA[16], qB[16];

    // ================= Phase B: norm + QKV (+qk-norm, rope) ================
    if (vA) {
        float qknQ[8], qknK[8];
#pragma unroll
        for (int e = 0; e < 8; e++) {
            qknQ[e] = sqkn[e] * (0.35355339059327373f * 1.4426950408889634f);
            qknK[e] = sqkn[8 + e];
        }
        float csA[4], snA[4], csB[4], snB[4];
        if (TEMPORAL) {
            const float th[4] = {1.f, 0.1f, 0.01f, 0.001f};
#pragma unroll
            for (int j = 0; j < 4; j++) {
                __sincosf((float)tokA * th[j], &snA[j], &csA[j]);
                __sincosf((float)tokB * th[j], &snB[j], &csB[j]);
            }
        }

        u64 hA[16], hB[16];
        {
            int gs = gseq0 + seqc;
            u64 x2[16];
#pragma unroll
            for (int which = 0; which < 2; which++) {
                int tok = which ? tokB : tokA;
                float* gx = which ? gxB : gxA;
                if (EMB0) {
                    // compute raw embedding + input rmsnorm; persist x to gmem
                    float raw[32];
                    if (tok < 64) {
                        float obsv = eobs[gs * 64 + tok];
                        const float4* de = (const float4*)(edimemb + tok * 32);
#pragma unroll
                        for (int c = 0; c < 8; c++) {
                            float4 dv = de[c];
                            raw[4 * c]     = fmaf(obsv, semb[4 * c],     semb[32 + 4 * c])     + dv.x;
                            raw[4 * c + 1] = fmaf(obsv, semb[4 * c + 1], semb[32 + 4 * c + 1]) + dv.y;
                            raw[4 * c + 2] = fmaf(obsv, semb[4 * c + 2], semb[32 + 4 * c + 2]) + dv.z;
                            raw[4 * c + 3] = fmaf(obsv, semb[4 * c + 3], semb[32 + 4 * c + 3]) + dv.w;
                        }
                    } else {
#pragma unroll
                        for (int d = 0; d < 32; d++) raw[d] = semb[96 + (tok - 64) * 32 + d];
                    }
                    float ss = 0.f;
#pragma unroll
                    for (int d = 0; d < 32; d++) ss = fmaf(raw[d], raw[d], ss);
                    float rs = rsqrtf(ss * 0.03125f + 1e-6f);
                    float4* go = (float4*)gx;
#pragma unroll
                    for (int c = 0; c < 8; c++) {
                        float x0 = raw[4 * c] * rs * semb[64 + 4 * c];
                        float x1 = raw[4 * c + 1] * rs * semb[64 + 4 * c + 1];
                        float x2v = raw[4 * c + 2] * rs * semb[64 + 4 * c + 2];
                        float x3 = raw[4 * c + 3] * rs * semb[64 + 4 * c + 3];
                        go[c] = make_float4(x0, x1, x2v, x3);
                        x2[2 * c] = pack2(x0, x1);
                        x2[2 * c + 1] = pack2(x2v, x3);
                    }
                } else {
                    ld_row16(x2, gx);
                }
                float rs = rsqrtf(sumsq16(x2) * 0.03125f + 1e-6f);
                u64 rs2 = pack2(rs, rs);
                const ulonglong2* nw = (const ulonglong2*)snorm;
                u64* h = which ? hB : hA;
#pragma unroll
                for (int i = 0; i < 8; i++) {
                    ulonglong2 n = nw[i];
                    h[2 * i] = mul2(mul2(x2[2 * i], rs2), n.x);
                    h[2 * i + 1] = mul2(mul2(x2[2 * i + 1], rs2), n.y);
                }
            }
        }

        // ---- K heads -> K^T ----
#pragma unroll 1
        for (int hh = 0; hh < 4; hh++) {
            float aA[8], aB[8];
#pragma unroll
            for (int e = 0; e < 8; e++) {
                float2 d = dot32x2(swk + (hh * 8 + e) * 32, hA, hB);
                aA[e] = d.x; aB[e] = d.y;
            }
            float msA = 0, msB = 0;
#pragma unroll
            for (int e = 0; e < 8; e++) { msA = fmaf(aA[e], aA[e], msA); msB = fmaf(aB[e], aB[e], msB); }
            float scA = rsqrtf(msA * 0.125f + 1e-6f);
            float scB = rsqrtf(msB * 0.125f + 1e-6f);
#pragma unroll
            for (int e = 0; e < 8; e++) { aA[e] *= scA * qknK[e]; aB[e] *= scB * qknK[e]; }
            if (TEMPORAL) {
#pragma unroll
                for (int e = 0; e < 4; e++) {
                    float t0 = aA[e], t1 = aA[e + 4];
                    aA[e] = t0 * csA[e] - t1 * snA[e];
                    aA[e + 4] = fmaf(t0, snA[e], t1 * csA[e]);
                    t0 = aB[e]; t1 = aB[e + 4];
                    aB[e] = t0 * csB[e] - t1 * snB[e];
                    aB[e + 4] = fmaf(t0, snB[e], t1 * csB[e]);
                }
            }
#pragma unroll
            for (int e = 0; e < 8; e++) {
                kT[(hh * 8 + e) * SP4 + tokA] = aA[e];
                if (vB) kT[(hh * 8 + e) * SP4 + tokB] = aB[e];
            }
        }

        // ---- V heads ----
#pragma unroll 1
        for (int hh = 0; hh < 4; hh++) {
            float aA[8], aB[8];
#pragma unroll
            for (int e = 0; e < 8; e++) {
                float2 d = dot32x2(swv + (hh * 8 + e) * 32, hA, hB);
                aA[e] = d.x; aB[e] = d.y;
            }
            float* dA = vb + tokA * ROW + hh * 8;
            *(float4*)dA = make_float4(aA[0], aA[1], aA[2], aA[3]);
            *(float4*)(dA + 4) = make_float4(aA[4], aA[5], aA[6], aA[7]);
            if (vB) {
                float* dB = vb + tokB * ROW + hh * 8;
                *(float4*)dB = make_float4(aB[0], aB[1], aB[2], aB[3]);
                *(float4*)(dB + 4) = make_float4(aB[4], aB[5], aB[6], aB[7]);
            }
        }

        // ---- Q heads ----
#pragma unroll
        for (int hh = 0; hh < 4; hh++) {
            float aA[8], aB[8];
#pragma unroll
            for (int e = 0; e < 8; e++) {
                float2 d = dot32x2(swq + (hh * 8 + e) * 32, hA, hB);
                aA[e] = d.x; aB[e] = d.y;
            }
            float msA = 0, msB = 0;
#pragma unroll
            for (int e = 0; e < 8; e++) { msA = fmaf(aA[e], aA[e], msA); msB = fmaf(aB[e], aB[e], msB); }
            float scA = rsqrtf(msA * 0.125f + 1e-6f);
            float scB = rsqrtf(msB * 0.125f + 1e-6f);
#pragma unroll
            for (int e = 0; e < 8; e++) { aA[e] *= scA * qknQ[e]; aB[e] *= scB * qknQ[e]; }
            if (TEMPORAL) {
#pragma unroll
                for (int e = 0; e < 4; e++) {
                    float t0 = aA[e], t1 = aA[e + 4];
                    aA[e] = t0 * csA[e] - t1 * snA[e];
                    aA[e + 4] = fmaf(t0, snA[e], t1 * csA[e]);
                    t0 = aB[e]; t1 = aB[e + 4];
                    aB[e] = t0 * csB[e] - t1 * snB[e];
                    aB[e + 4] = fmaf(t0, snB[e], t1 * csB[e]);
                }
            }
#pragma unroll
            for (int j = 0; j < 4; j++) {
                qA[4 * hh + j] = pack2(aA[2 * j], aA[2 * j + 1]);
                qB[4 * hh + j] = pack2(aB[2 * j], aB[2 * j + 1]);
            }
        }
    }
    __syncthreads();

    // ====== Phase C: packed-score attention, two head-split passes =========
    u64 oA[16], oB[16];
    if (vA) {
#pragma unroll
        for (int pass = 0; pass < 2; pass++) {
            u64 qdA[16], qdB[16];
#pragma unroll
            for (int i = 0; i < 8; i++) {
                float lo, hi;
                unpk(qA[8 * pass + i], lo, hi);
                qdA[2 * i] = pack2(lo, lo); qdA[2 * i + 1] = pack2(hi, hi);
                unpk(qB[8 * pass + i], lo, hi);
                qdB[2 * i] = pack2(lo, lo); qdB[2 * i + 1] = pack2(hi, hi);
            }
            u64 aA[8], aB[8];
#pragma unroll
            for (int i = 0; i < 8; i++) { aA[i] = 0ULL; aB[i] = 0ULL; }
            float l0A = 0.f, l1A = 0.f, l0B = 0.f, l1B = 0.f;
            const float* kTp = kT + (16 * pass) * SP4;
            const float* vp = vb + 16 * pass;

#pragma unroll 2
            for (int jb = 0; jb < SP4; jb += 4) {
                u64 sA0a = 0, sA0b = 0, sA1a = 0, sA1b = 0;
                u64 sB0a = 0, sB0b = 0, sB1a = 0, sB1b = 0;
#pragma unroll
                for (int d = 0; d < 8; d++) {
                    ulonglong2 t0 = *(const ulonglong2*)(kTp + d * SP4 + jb);
                    ulonglong2 t1 = *(const ulonglong2*)(kTp + (d + 8) * SP4 + jb);
                    sA0a = fma2(qdA[d], t0.x, sA0a); sA0b = fma2(qdA[d], t0.y, sA0b);
                    sB0a = fma2(qdB[d], t0.x, sB0a); sB0b = fma2(qdB[d], t0.y, sB0b);
                    sA1a = fma2(qdA[8 + d], t1.x, sA1a); sA1b = fma2(qdA[8 + d], t1.y, sA1b);
                    sB1a = fma2(qdB[8 + d], t1.x, sB1a); sB1b = fma2(qdB[8 + d], t1.y, sB1b);
                }
                float pA0[4], pA1[4], pB0[4], pB1[4];
                unpk(sA0a, pA0[0], pA0[1]); unpk(sA0b, pA0[2], pA0[3]);
                unpk(sA1a, pA1[0], pA1[1]); unpk(sA1b, pA1[2], pA1[3]);
                unpk(sB0a, pB0[0], pB0[1]); unpk(sB0b, pB0[2], pB0[3]);
                unpk(sB1a, pB1[0], pB1[1]); unpk(sB1b, pB1[2], pB1[3]);
#pragma unroll
                for (int jj = 0; jj < 4; jj++) {
                    pA0[jj] = ex2f(pA0[jj]); l0A += pA0[jj];
                    pA1[jj] = ex2f(pA1[jj]); l1A += pA1[jj];
                    pB0[jj] = ex2f(pB0[jj]); l0B += pB0[jj];
                    pB1[jj] = ex2f(pB1[jj]); l1B += pB1[jj];
                }
#pragma unroll
                for (int jj = 0; jj < 4; jj++) {
                    const ulonglong2* vr = (const ulonglong2*)(vp + (jb + jj) * ROW);
                    ulonglong2 v0 = vr[0], v1 = vr[1], v2 = vr[2], v3 = vr[3];
                    u64 pp;
                    pp = pack2(pA0[jj], pA0[jj]);
                    aA[0] = fma2(pp, v0.x, aA[0]); aA[1] = fma2(pp, v0.y, aA[1]);
                    aA[2] = fma2(pp, v1.x, aA[2]); aA[3] = fma2(pp, v1.y, aA[3]);
                    pp = pack2(pA1[jj], pA1[jj]);
                    aA[4] = fma2(pp, v2.x, aA[4]); aA[5] = fma2(pp, v2.y, aA[5]);
                    aA[6] = fma2(pp, v3.x, aA[6]); aA[7] = fma2(pp, v3.y, aA[7]);
                    pp = pack2(pB0[jj], pB0[jj]);
                    aB[0] = fma2(pp, v0.x, aB[0]); aB[1] = fma2(pp, v0.y, aB[1]);
                    aB[2] = fma2(pp, v1.x, aB[2]); aB[3] = fma2(pp, v1.y, aB[3]);
                    pp = pack2(pB1[jj], pB1[jj]);
                    aB[4] = fma2(pp, v2.x, aB[4]); aB[5] = fma2(pp, v2.y, aB[5]);
                    aB[6] = fma2(pp, v3.x, aB[6]); aB[7] = fma2(pp, v3.y, aB[7]);
                }
            }
            l0A -= (float)PADK; l1A -= (float)PADK;
            l0B -= (float)PADK; l1B -= (float)PADK;

            float i0A = __fdividef(1.f, l0A), i1A = __fdividef(1.f, l1A);
            float i0B = __fdividef(1.f, l0B), i1B = __fdividef(1.f, l1B);
            u64 z;
            z = pack2(i0A, i0A);
#pragma unroll
            for (int i = 0; i < 4; i++) oA[8 * pass + i] = mul2(aA[i], z);
            z = pack2(i1A, i1A);
#pragma unroll
            for (int i = 4; i < 8; i++) oA[8 * pass + i] = mul2(aA[i], z);
            z = pack2(i0B, i0B);
#pragma unroll
            for (int i = 0; i < 4; i++) oB[8 * pass + i] = mul2(aB[i], z);
            z = pack2(i1B, i1B);
#pragma unroll
            for (int i = 4; i < 8; i++) oB[8 * pass + i] = mul2(aB[i], z);
        }
    }
    __syncthreads();   // K^T/V consumed -> K^T block reusable for FFN weights

    // ---- late-stage FFN weights into the dead K^T block ----
    for (int i = tid; i < 512; i += BLK) {
        ((float4*)swg2)[i] = ((const float4*)Wg)[i];
        ((float4*)swu2)[i] = ((const float4*)Wu)[i];
    }
    for (int i = tid; i < 2048; i += BLK) {
        int f = i >> 5, d = i & 31;
        swout2[i] = Wout[d * 64 + f];
    }

    // ================= Phase D: Wo + residual (overlaps FFN staging) =======
    u64 h2A[16], h2B[16];
    if (vA) {
        float owA[32], owB[32];
        float ssA = 0.f, ssB = 0.f;
#pragma unroll
        for (int d = 0; d < 32; d++) {
            float2 r = dot32x2(swo + d * 32, oA, oB);
            owA[d] = r.x; owB[d] = r.y;
            ssA = fmaf(r.x, r.x, ssA);
            ssB = fmaf(r.y, r.y, ssB);
        }
        float rAs = rsqrtf(ssA * 0.03125f + 1e-6f);
        float rBs = rsqrtf(ssB * 0.03125f + 1e-6f);
        u64 rsA = pack2(rAs, rAs);
        u64 rsB = pack2(rBs, rBs);

        u64 x2[16], xn[16];
        const ulonglong2* nw1 = (const ulonglong2*)(snorm + 32);
        const ulonglong2* nw2 = (const ulonglong2*)(snorm + 64);
        ld_row16(x2, gxA);
#pragma unroll
        for (int i = 0; i < 8; i++) {
            ulonglong2 n = nw1[i];
            xn[2 * i] = fma2(mul2(pack2(owA[4 * i], owA[4 * i + 1]), rsA), n.x, x2[2 * i]);
            xn[2 * i + 1] = fma2(mul2(pack2(owA[4 * i + 2], owA[4 * i + 3]), rsA), n.y, x2[2 * i + 1]);
        }
        {
            ulonglong2* xo = (ulonglong2*)(vb + tokA * ROW);
#pragma unroll
            for (int i = 0; i < 8; i++) { ulonglong2 t; t.x = xn[2 * i]; t.y = xn[2 * i + 1]; xo[i] = t; }
        }
        float rsa = rsqrtf(sumsq16(xn) * 0.03125f + 1e-6f);
        u64 rsa2 = pack2(rsa, rsa);
#pragma unroll
        for (int i = 0; i < 8; i++) {
            ulonglong2 n = nw2[i];
            h2A[2 * i] = mul2(mul2(xn[2 * i], rsa2), n.x);
            h2A[2 * i + 1] = mul2(mul2(xn[2 * i + 1], rsa2), n.y);
        }
        // token B
        ld_row16(x2, gxB);
#pragma unroll
        for (int i = 0; i < 8; i++) {
            ulonglong2 n = nw1[i];
            xn[2 * i] = fma2(mul2(pack2(owB[4 * i], owB[4 * i + 1]), rsB), n.x, x2[2 * i]);
            xn[2 * i + 1] = fma2(mul2(pack2(owB[4 * i + 2], owB[4 * i + 3]), rsB), n.y, x2[2 * i + 1]);
        }
        if (vB) {
            ulonglong2* xo = (ulonglong2*)(vb + tokB * ROW);
#pragma unroll
            for (int i = 0; i < 8; i++) { ulonglong2 t; t.x = xn[2 * i]; t.y = xn[2 * i + 1]; xo[i] = t; }
        }
        float rsb = rsqrtf(sumsq16(xn) * 0.03125f + 1e-6f);
        u64 rsb2 = pack2(rsb, rsb);
#pragma unroll
        for (int i = 0; i < 8; i++) {
            ulonglong2 n = nw2[i];
            h2B[2 * i] = mul2(mul2(xn[2 * i], rsb2), n.x);
            h2B[2 * i + 1] = mul2(mul2(xn[2 * i + 1], rsb2), n.y);
        }
    }
    __syncthreads();   // FFN weights visible; xn stashed in V rows

    // ================= Phase E: FFN + residual -> gmem =====================
    if (vA) {
        u64 ovA[16], ovB[16];
#pragma unroll
        for (int i = 0; i < 16; i++) { ovA[i] = 0ULL; ovB[i] = 0ULL; }

#pragma unroll 1
        for (int fg = 0; fg < 16; fg++) {
#pragma unroll
            for (int e = 0; e < 4; e++) {
                int f = fg * 4 + e;
                float2 g2 = dot32x2(swg2 + f * 32, h2A, h2B);
                float2 u2 = dot32x2(swu2 + f * 32, h2A, h2B);
                float fvA = __fdividef(g2.x, 1.f + __expf(-g2.x)) * u2.x;
                float fvB = __fdividef(g2.y, 1.f + __expf(-g2.y)) * u2.y;
                u64 fA = pack2(fvA, fvA), fB = pack2(fvB, fvB);
                const ulonglong2* wr = (const ulonglong2*)(swout2 + f * 32);
#pragma unroll
                for (int i = 0; i < 8; i++) {
                    ulonglong2 t = wr[i];
                    ovA[2 * i] = fma2(fA, t.x, ovA[2 * i]);
                    ovA[2 * i + 1] = fma2(fA, t.y, ovA[2 * i + 1]);
                    ovB[2 * i] = fma2(fB, t.x, ovB[2 * i]);
                    ovB[2 * i + 1] = fma2(fB, t.y, ovB[2 * i + 1]);
                }
            }
        }

        // out = xn + rmsnorm(ov): reload xn from V rows, write gmem
        const ulonglong2* nw = (const ulonglong2*)(snorm + 96);
        float rs3 = rsqrtf(sumsq16(ovA) * 0.03125f + 1e-6f);
        u64 rs32 = pack2(rs3, rs3);
        u64 xn[16];
        ld_row16(xn, vb + tokA * ROW);
        ulonglong2* go = (ulonglong2*)gxA;
#pragma unroll
        for (int i = 0; i < 8; i++) {
            ulonglong2 n = nw[i];
            ulonglong2 r;
            r.x = fma2(mul2(ovA[2 * i], rs32), n.x, xn[2 * i]);
            r.y = fma2(mul2(ovA[2 * i + 1], rs32), n.y, xn[2 * i + 1]);
            go[i] = r;
        }
        if (vB) {
            rs3 = rsqrtf(sumsq16(ovB) * 0.03125f + 1e-6f);
            rs32 = pack2(rs3, rs3);
            ld_row16(xn, vb + tokB * ROW);
            go = (ulonglong2*)gxB;
#pragma unroll
            for (int i = 0; i < 8; i++) {
                ulonglong2 n = nw[i];
                ulonglong2 r;
                r.x = fma2(mul2(ovB[2 * i], rs32), n.x, xn[2 * i]);
                r.y = fma2(mul2(ovB[2 * i + 1], rs32), n.y, xn[2 * i + 1]);
                go[i] = r;
            }
        }
    }
}

// ---------------------------------------------------------------------------
// Final: rmsnorm + extract 3 CLS tokens of last timestep.
// ---------------------------------------------------------------------------
__global__ void final_kernel(const float* __restrict__ fnorm, float* __restrict__ out) {
    int b = blockIdx.x / 3, k = blockIdx.x % 3, lane = threadIdx.x;
    float x = g_tokens[(((long)b * 128 + 127) * 67 + 64 + k) * 32 + lane];
    float ms = warp_sum(x * x) * (1.f / 32.f);
    out[(k * 16 + b) * 32 + lane] = x * rsqrtf(ms + 1e-6f) * fnorm[lane];
}

// ---------------------------------------------------------------------------
// Launch
// ---------------------------------------------------------------------------
extern "C" void kernel_launch(void* const* d_in, const int* in_sizes, int n_in,
                              void* d_out, int out_size) {
    const float* obs    = (const float*)d_in[0];
    const float* Wval   = (const float*)d_in[1];
    const float* bval   = (const float*)d_in[2];
    const float* innorm = (const float*)d_in[3];
    const float* dimemb = (const float*)d_in[4];
    const float* cls    = (const float*)d_in[5];
    const float* fnorm  = (const float*)d_in[6];
    const float* sWq   = (const float*)d_in[7];
    const float* sWk   = (const float*)d_in[8];
    const float* sWv   = (const float*)d_in[9];
    const float* sWo   = (const float*)d_in[10];
    const float* sWg   = (const float*)d_in[11];
    const float* sWu   = (const float*)d_in[12];
    const float* sWout = (const float*)d_in[13];
    const float* sN4   = (const float*)d_in[14];
    const float* sQKN  = (const float*)d_in[15];
    const float* tWq   = (const float*)d_in[16];
    const float* tWk   = (const float*)d_in[17];
    const float* tWv   = (const float*)d_in[18];
    const float* tWo   = (const float*)d_in[19];
    const float* tWg   = (const float*)d_in[20];
    const float* tWu   = (const float*)d_in[21];
    const float* tWout = (const float*)d_in[22];
    const float* tN4   = (const float*)d_in[23];
    const float* tQKN  = (const float*)d_in[24];

    // spatial: 3*(32*68+68*36) + 4096 + 144 + 192 = 18304 fl = 73216 B
    // temporal: 4*(32*128+128*36) + 4096 + 144 + 192 = 39248 fl = 156992 B
    const int SZ_S = (3 * (32 * 68 + 68 * 36) + 4096 + 144 + 192) * 4;
    const int SZ_T = (4 * (32 * 128 + 128 * 36) + 4096 + 144 + 192) * 4;

    cudaFuncSetAttribute(attn_tpl<67, 3, false, true>, cudaFuncAttributeMaxDynamicSharedMemorySize, SZ_S);
    cudaFuncSetAttribute(attn_tpl<67, 3, false, false>, cudaFuncAttributeMaxDynamicSharedMemorySize, SZ_S);
    cudaFuncSetAttribute(attn_tpl<128, 4, true, false>, cudaFuncAttributeMaxDynamicSharedMemorySize, SZ_T);

    const int GRID_S = (2048 + 2) / 3;   // 683
    const int GRID_T = 1072 / 4;         // 268

    for (int layer = 0; layer < 3; layer++) {
        if (layer == 0) {
            attn_tpl<67, 3, false, true><<<GRID_S, 128, SZ_S>>>(
                sWq, sWk, sWv, sWo, sWg, sWu, sWout, sN4, sQKN, 2048,
                obs, Wval, bval, innorm, dimemb, cls);
        } else {
            attn_tpl<67, 3, false, false><<<GRID_S, 128, SZ_S>>>(
                sWq + layer * 1024, sWk + layer * 1024, sWv + layer * 1024, sWo + layer * 1024,
                sWg + layer * 2048, sWu + layer * 2048, sWout + layer * 2048,
                sN4 + layer * 128, sQKN + layer * 16, 2048,
                nullptr, nullptr, nullptr, nullptr, nullptr, nullptr);
        }
        if (layer < 2) {
            attn_tpl<128, 4, true, false><<<GRID_T, 256, SZ_T>>>(
                tWq + layer * 1024, tWk + layer * 1024, tWv + layer * 1024, tWo + layer * 1024,
                tWg + layer * 2048, tWu + layer * 2048, tWout + layer * 2048,
                tN4 + layer * 128, tQKN + layer * 16, 1072,
                nullptr, nullptr, nullptr, nullptr, nullptr, nullptr);
        }
    }

    final_kernel<<<48, 32>>>(fnorm, (float*)d_out);
}

// round 16
// speedup vs baseline: 1.0515x; 1.0515x over previous
#include <cuda_runtime.h>
#include <math.h>

#define FULL 0xffffffffu
typedef unsigned long long u64;

// Scratch token buffer: (B=16, T=128, slots=67, EMBED=32) fp32
__device__ float g_tokens[16 * 128 * 67 * 32];

__device__ __forceinline__ float warp_sum(float v) {
    v += __shfl_xor_sync(FULL, v, 16);
    v += __shfl_xor_sync(FULL, v, 8);
    v += __shfl_xor_sync(FULL, v, 4);
    v += __shfl_xor_sync(FULL, v, 2);
    v += __shfl_xor_sync(FULL, v, 1);
    return v;
}

// ---- packed f32x2 helpers ----
__device__ __forceinline__ u64 fma2(u64 a, u64 b, u64 c) {
    u64 d; asm("fma.rn.f32x2 %0, %1, %2, %3;" : "=l"(d) : "l"(a), "l"(b), "l"(c)); return d;
}
__device__ __forceinline__ u64 mul2(u64 a, u64 b) {
    u64 d; asm("mul.rn.f32x2 %0, %1, %2;" : "=l"(d) : "l"(a), "l"(b)); return d;
}
__device__ __forceinline__ u64 add2(u64 a, u64 b) {
    u64 d; asm("add.rn.f32x2 %0, %1, %2;" : "=l"(d) : "l"(a), "l"(b)); return d;
}
__device__ __forceinline__ u64 pack2(float lo, float hi) {
    u64 d; asm("mov.b64 %0, {%1, %2};" : "=l"(d) : "f"(lo), "f"(hi)); return d;
}
__device__ __forceinline__ float hsum2(u64 v) {
    float lo, hi; asm("mov.b64 {%0, %1}, %2;" : "=f"(lo), "=f"(hi) : "l"(v)); return lo + hi;
}
__device__ __forceinline__ void unpk(u64 v, float& a, float& b) {
    asm("mov.b64 {%0, %1}, %2;" : "=f"(a), "=f"(b) : "l"(v));
}
// base-2 exp, scores pre-scaled by log2(e)
__device__ __forceinline__ float ex2f(float x) {
    float y; asm("ex2.approx.f32 %0, %1;" : "=f"(y) : "f"(x)); return y;
}

__device__ __forceinline__ void ld_row16(u64* r, const float* p) {
    const ulonglong2* q = (const ulonglong2*)p;
#pragma unroll
    for (int i = 0; i < 8; i++) { ulonglong2 t = q[i]; r[2 * i] = t.x; r[2 * i + 1] = t.y; }
}

// one weight row read, TWO dots (token pair)
__device__ __forceinline__ float2 dot32x2(const float* wrow, const u64* a, const u64* b) {
    const ulonglong2* w = (const ulonglong2*)wrow;
    ulonglong2 t0 = w[0], t1 = w[1];
    u64 a0 = mul2(a[0], t0.x), b0 = mul2(b[0], t0.x);
    a0 = fma2(a[1], t0.y, a0); b0 = fma2(b[1], t0.y, b0);
    u64 a1 = mul2(a[2], t1.x), b1 = mul2(b[2], t1.x);
    a1 = fma2(a[3], t1.y, a1); b1 = fma2(b[3], t1.y, b1);
#pragma unroll
    for (int i = 2; i < 8; i += 2) {
        ulonglong2 u0 = w[i], u1 = w[i + 1];
        a0 = fma2(a[2 * i], u0.x, a0);     b0 = fma2(b[2 * i], u0.x, b0);
        a0 = fma2(a[2 * i + 1], u0.y, a0); b0 = fma2(b[2 * i + 1], u0.y, b0);
        a1 = fma2(a[2 * i + 2], u1.x, a1); b1 = fma2(b[2 * i + 2], u1.x, b1);
        a1 = fma2(a[2 * i + 3], u1.y, a1); b1 = fma2(b[2 * i + 3], u1.y, b1);
    }
    return make_float2(hsum2(add2(a0, a1)), hsum2(add2(b0, b1)));
}

__device__ __forceinline__ float sumsq16(const u64* v) {
    u64 a0 = mul2(v[0], v[0]);
    u64 a1 = mul2(v[1], v[1]);
#pragma unroll
    for (int i = 2; i < 16; i += 2) {
        a0 = fma2(v[i], v[i], a0);
        a1 = fma2(v[i + 1], v[i + 1], a1);
    }
    return hsum2(add2(a0, a1));
}

// ---------------------------------------------------------------------------
// Monolithic fused block (R12 structure). Transposed-K packed-score attention;
// 2 tokens/lane; two head-split passes; base-2 softmax; unroll 1 everywhere.
// EMB0: layer-0 spatial computes token embedding + input rmsnorm in-kernel
// (fusing the embed kernel) and persists x to g_tokens for the phase-D reload.
// ---------------------------------------------------------------------------
template <int S, int NSEQ, bool TEMPORAL, bool EMB0>
__global__ void __launch_bounds__(32 * ((((S + 1) / 2) * NSEQ + 31) / 32))
attn_tpl(const float* __restrict__ Wq, const float* __restrict__ Wk,
         const float* __restrict__ Wv, const float* __restrict__ Wo,
         const float* __restrict__ Wg, const float* __restrict__ Wu,
         const float* __restrict__ Wout, const float* __restrict__ norm4,
         const float* __restrict__ qkn, int nseq_total,
         const float* __restrict__ eobs, const float* __restrict__ eWval,
         const float* __restrict__ ebval, const float* __restrict__ einnorm,
         const float* __restrict__ edimemb, const float* __restrict__ ecls) {
    constexpr int HS = (S + 1) / 2;
    constexpr int BLK = 32 * ((HS * NSEQ + 31) / 32);
    constexpr int SP4 = ((S + 3) / 4) * 4;       // keys padded to mult of 4
    constexpr int PADK = SP4 - S;
    constexpr int ROW = 36;                      // V row stride
    constexpr int KTSZ = 32 * SP4;               // K^T area per seq
    constexpr int SEQSTR = KTSZ + SP4 * ROW;
    constexpr int DATSZ = NSEQ * SEQSTR;

    extern __shared__ float sm[];
    float* skv   = sm;                 // DATSZ
    float* swq   = skv + DATSZ;        // 1024
    float* swk   = swq + 1024;
    float* swv   = swk + 1024;
    float* swo   = swv + 1024;
    float* swg   = swo + 1024;         // 2048
    float* swu   = swg + 2048;         // 2048
    float* swout = swu + 2048;         // 2048 transposed [f][d]
    float* snorm = swout + 2048;       // 128
    float* sqkn  = snorm + 128;        // 16
    float* semb  = sqkn + 16;          // 192 (Wval,bval,innorm,cls)

    const int tid = threadIdx.x;
    int gseq0 = blockIdx.x * NSEQ;

    // ---- stage weights ----
    for (int i = tid; i < 256; i += BLK) {
        ((float4*)swq)[i] = ((const float4*)Wq)[i];
        ((float4*)swk)[i] = ((const float4*)Wk)[i];
        ((float4*)swv)[i] = ((const float4*)Wv)[i];
        ((float4*)swo)[i] = ((const float4*)Wo)[i];
    }
    for (int i = tid; i < 512; i += BLK) {
        ((float4*)swg)[i] = ((const float4*)Wg)[i];
        ((float4*)swu)[i] = ((const float4*)Wu)[i];
    }
    for (int i = tid; i < 2048; i += BLK) {   // transpose Wout -> [f][d]
        int f = i >> 5, d = i & 31;
        swout[i] = Wout[d * 64 + f];
    }
    if (tid < 128) snorm[tid] = norm4[tid];
    if (tid < 16) sqkn[tid] = qkn[tid];
    if (EMB0) {
        if (tid < 32) {
            semb[tid] = eWval[tid];
            semb[32 + tid] = ebval[tid];
            semb[64 + tid] = einnorm[tid];
        }
        if (tid < 96) semb[96 + tid] = ecls[tid];
    }

    // ---- zero pad keys: K^T columns S..SP4-1 (32 dims) + V rows S..SP4-1 --
    if (PADK > 0) {
        constexpr int PER = (32 + ROW) * PADK;
        for (int i = tid; i < NSEQ * PER; i += BLK) {
            int sq = i / PER;
            int r = i - sq * PER;
            float* sb = skv + sq * SEQSTR;
            if (r < 32 * PADK) {
                int d = r / PADK, pc = r - d * PADK;
                sb[d * SP4 + S + pc] = 0.f;
            } else {
                int rr = r - 32 * PADK;
                sb[KTSZ + (S + rr / ROW) * ROW + rr % ROW] = 0.f;
            }
        }
    }

    // ---- token-pair assignment ----
    int seq = tid / HS;
    int l = tid - seq * HS;
    bool seqok = (seq < NSEQ) && (gseq0 + seq < nseq_total);
    int seqc = seqok ? seq : 0;
    bool vA = seqok;
    bool vB = seqok && (l + HS < S);
    int tokA = l;
    int tokB = vB ? (l + HS) : (S - 1);

    float* kT = skv + seqc * SEQSTR;
    float* vb = kT + KTSZ;

    float *gxA, *gxB;
    {
        int gs = gseq0 + seqc;
        if (TEMPORAL) {
            int b = gs / 67, sl = gs - b * 67;
            gxA = g_tokens + ((long)(b * 128 + tokA) * 67 + sl) * 32;
            gxB = g_tokens + ((long)(b * 128 + tokB) * 67 + sl) * 32;
        } else {
            gxA = g_tokens + ((long)gs * 67 + tokA) * 32;
            gxB = g_tokens + ((long)gs * 67 + tokB) * 32;
        }
    }

    __syncthreads();

    u64 qA[16], qB[16];

    // ================= Phase B: norm + QKV (+qk-norm, rope) ================
    if (vA) {
        float qknQ[8], qknK[8];
#pragma unroll
        for (int e = 0; e < 8; e++) {
            qknQ[e] = sqkn[e] * (0.35355339059327373f * 1.4426950408889634f);
            qknK[e] = sqkn[8 + e];
        }
        float csA[4], snA[4], csB[4], snB[4];
        if (TEMPORAL) {
            const float th[4] = {1.f, 0.1f, 0.01f, 0.001f};
#pragma unroll
            for (int j = 0; j < 4; j++) {
                __sincosf((float)tokA * th[j], &snA[j], &csA[j]);
                __sincosf((float)tokB * th[j], &snB[j], &csB[j]);
            }
        }

        u64 hA[16], hB[16];
        {
            int gs = gseq0 + seqc;
            u64 x2[16];
#pragma unroll
            for (int which = 0; which < 2; which++) {
                int tok = which ? tokB : tokA;
                float* gx = which ? gxB : gxA;
                if (EMB0) {
                    float raw[32];
                    if (tok < 64) {
                        float obsv = eobs[gs * 64 + tok];
                        const float4* de = (const float4*)(edimemb + tok * 32);
#pragma unroll
                        for (int c = 0; c < 8; c++) {
                            float4 dv = de[c];
                            raw[4 * c]     = fmaf(obsv, semb[4 * c],     semb[32 + 4 * c])     + dv.x;
                            raw[4 * c + 1] = fmaf(obsv, semb[4 * c + 1], semb[32 + 4 * c + 1]) + dv.y;
                            raw[4 * c + 2] = fmaf(obsv, semb[4 * c + 2], semb[32 + 4 * c + 2]) + dv.z;
                            raw[4 * c + 3] = fmaf(obsv, semb[4 * c + 3], semb[32 + 4 * c + 3]) + dv.w;
                        }
                    } else {
#pragma unroll
                        for (int d = 0; d < 32; d++) raw[d] = semb[96 + (tok - 64) * 32 + d];
                    }
                    float ss = 0.f;
#pragma unroll
                    for (int d = 0; d < 32; d++) ss = fmaf(raw[d], raw[d], ss);
                    float rsx = rsqrtf(ss * 0.03125f + 1e-6f);
                    float4* go = (float4*)gx;
#pragma unroll
                    for (int c = 0; c < 8; c++) {
                        float x0 = raw[4 * c] * rsx * semb[64 + 4 * c];
                        float x1 = raw[4 * c + 1] * rsx * semb[64 + 4 * c + 1];
                        float x2v = raw[4 * c + 2] * rsx * semb[64 + 4 * c + 2];
                        float x3 = raw[4 * c + 3] * rsx * semb[64 + 4 * c + 3];
                        go[c] = make_float4(x0, x1, x2v, x3);
                        x2[2 * c] = pack2(x0, x1);
                        x2[2 * c + 1] = pack2(x2v, x3);
                    }
                } else {
                    ld_row16(x2, gx);
                }
                float rs = rsqrtf(sumsq16(x2) * 0.03125f + 1e-6f);
                u64 rs2 = pack2(rs, rs);
                const ulonglong2* nw = (const ulonglong2*)snorm;
                u64* h = which ? hB : hA;
#pragma unroll
                for (int i = 0; i < 8; i++) {
                    ulonglong2 n = nw[i];
                    h[2 * i] = mul2(mul2(x2[2 * i], rs2), n.x);
                    h[2 * i + 1] = mul2(mul2(x2[2 * i + 1], rs2), n.y);
                }
            }
        }

        // ---- K heads: store into K^T (keys contiguous) ----
#pragma unroll 1
        for (int hh = 0; hh < 4; hh++) {
            float aA[8], aB[8];
#pragma unroll
            for (int e = 0; e < 8; e++) {
                float2 d = dot32x2(swk + (hh * 8 + e) * 32, hA, hB);
                aA[e] = d.x; aB[e] = d.y;
            }
            float msA = 0, msB = 0;
#pragma unroll
            for (int e = 0; e < 8; e++) { msA = fmaf(aA[e], aA[e], msA); msB = fmaf(aB[e], aB[e], msB); }
            float scA = rsqrtf(msA * 0.125f + 1e-6f);
            float scB = rsqrtf(msB * 0.125f + 1e-6f);
#pragma unroll
            for (int e = 0; e < 8; e++) { aA[e] *= scA * qknK[e]; aB[e] *= scB * qknK[e]; }
            if (TEMPORAL) {
#pragma unroll
                for (int e = 0; e < 4; e++) {
                    float t0 = aA[e], t1 = aA[e + 4];
                    aA[e] = t0 * csA[e] - t1 * snA[e];
                    aA[e + 4] = fmaf(t0, snA[e], t1 * csA[e]);
                    t0 = aB[e]; t1 = aB[e + 4];
                    aB[e] = t0 * csB[e] - t1 * snB[e];
                    aB[e + 4] = fmaf(t0, snB[e], t1 * csB[e]);
                }
            }
#pragma unroll
            for (int e = 0; e < 8; e++) {
                kT[(hh * 8 + e) * SP4 + tokA] = aA[e];
                if (vB) kT[(hh * 8 + e) * SP4 + tokB] = aB[e];
            }
        }

        // ---- V heads (row-major) ----
#pragma unroll 1
        for (int hh = 0; hh < 4; hh++) {
            float aA[8], aB[8];
#pragma unroll
            for (int e = 0; e < 8; e++) {
                float2 d = dot32x2(swv + (hh * 8 + e) * 32, hA, hB);
                aA[e] = d.x; aB[e] = d.y;
            }
            float* dA = vb + tokA * ROW + hh * 8;
            *(float4*)dA = make_float4(aA[0], aA[1], aA[2], aA[3]);
            *(float4*)(dA + 4) = make_float4(aA[4], aA[5], aA[6], aA[7]);
            if (vB) {
                float* dB = vb + tokB * ROW + hh * 8;
                *(float4*)dB = make_float4(aB[0], aB[1], aB[2], aB[3]);
                *(float4*)(dB + 4) = make_float4(aB[4], aB[5], aB[6], aB[7]);
            }
        }

        // ---- Q heads ----
#pragma unroll
        for (int hh = 0; hh < 4; hh++) {
            float aA[8], aB[8];
#pragma unroll
            for (int e = 0; e < 8; e++) {
                float2 d = dot32x2(swq + (hh * 8 + e) * 32, hA, hB);
                aA[e] = d.x; aB[e] = d.y;
            }
            float msA = 0, msB = 0;
#pragma unroll
            for (int e = 0; e < 8; e++) { msA = fmaf(aA[e], aA[e], msA); msB = fmaf(aB[e], aB[e], msB); }
            float scA = rsqrtf(msA * 0.125f + 1e-6f);
            float scB = rsqrtf(msB * 0.125f + 1e-6f);
#pragma unroll
            for (int e = 0; e < 8; e++) { aA[e] *= scA * qknQ[e]; aB[e] *= scB * qknQ[e]; }
            if (TEMPORAL) {
#pragma unroll
                for (int e = 0; e < 4; e++) {
                    float t0 = aA[e], t1 = aA[e + 4];
                    aA[e] = t0 * csA[e] - t1 * snA[e];
                    aA[e + 4] = fmaf(t0, snA[e], t1 * csA[e]);
                    t0 = aB[e]; t1 = aB[e + 4];
                    aB[e] = t0 * csB[e] - t1 * snB[e];
                    aB[e + 4] = fmaf(t0, snB[e], t1 * csB[e]);
                }
            }
#pragma unroll
            for (int j = 0; j < 4; j++) {
                qA[4 * hh + j] = pack2(aA[2 * j], aA[2 * j + 1]);
                qB[4 * hh + j] = pack2(aB[2 * j], aB[2 * j + 1]);
            }
        }
    }
    __syncthreads();

    // ====== Phase C: packed-score attention, two head-split passes =========
    u64 oA[16], oB[16];
    if (vA) {
#pragma unroll
        for (int pass = 0; pass < 2; pass++) {
            u64 qdA[16], qdB[16];
#pragma unroll
            for (int i = 0; i < 8; i++) {
                float lo, hi;
                unpk(qA[8 * pass + i], lo, hi);
                qdA[2 * i] = pack2(lo, lo); qdA[2 * i + 1] = pack2(hi, hi);
                unpk(qB[8 * pass + i], lo, hi);
                qdB[2 * i] = pack2(lo, lo); qdB[2 * i + 1] = pack2(hi, hi);
            }
            u64 aA[8], aB[8];
#pragma unroll
            for (int i = 0; i < 8; i++) { aA[i] = 0ULL; aB[i] = 0ULL; }
            float l0A = 0.f, l1A = 0.f, l0B = 0.f, l1B = 0.f;
            const float* kTp = kT + (16 * pass) * SP4;
            const float* vp = vb + 16 * pass;

#pragma unroll 1
            for (int jb = 0; jb < SP4; jb += 4) {
                u64 sA0a = 0, sA0b = 0, sA1a = 0, sA1b = 0;
                u64 sB0a = 0, sB0b = 0, sB1a = 0, sB1b = 0;
#pragma unroll
                for (int d = 0; d < 8; d++) {
                    ulonglong2 t0 = *(const ulonglong2*)(kTp + d * SP4 + jb);
                    ulonglong2 t1 = *(const ulonglong2*)(kTp + (d + 8) * SP4 + jb);
                    sA0a = fma2(qdA[d], t0.x, sA0a); sA0b = fma2(qdA[d], t0.y, sA0b);
                    sB0a = fma2(qdB[d], t0.x, sB0a); sB0b = fma2(qdB[d], t0.y, sB0b);
                    sA1a = fma2(qdA[8 + d], t1.x, sA1a); sA1b = fma2(qdA[8 + d], t1.y, sA1b);
                    sB1a = fma2(qdB[8 + d], t1.x, sB1a); sB1b = fma2(qdB[8 + d], t1.y, sB1b);
                }
                float pA0[4], pA1[4], pB0[4], pB1[4];
                unpk(sA0a, pA0[0], pA0[1]); unpk(sA0b, pA0[2], pA0[3]);
                unpk(sA1a, pA1[0], pA1[1]); unpk(sA1b, pA1[2], pA1[3]);
                unpk(sB0a, pB0[0], pB0[1]); unpk(sB0b, pB0[2], pB0[3]);
                unpk(sB1a, pB1[0], pB1[1]); unpk(sB1b, pB1[2], pB1[3]);
#pragma unroll
                for (int jj = 0; jj < 4; jj++) {
                    pA0[jj] = ex2f(pA0[jj]); l0A += pA0[jj];
                    pA1[jj] = ex2f(pA1[jj]); l1A += pA1[jj];
                    pB0[jj] = ex2f(pB0[jj]); l0B += pB0[jj];
                    pB1[jj] = ex2f(pB1[jj]); l1B += pB1[jj];
                }
#pragma unroll
                for (int jj = 0; jj < 4; jj++) {
                    const ulonglong2* vr = (const ulonglong2*)(vp + (jb + jj) * ROW);
                    ulonglong2 v0 = vr[0], v1 = vr[1], v2 = vr[2], v3 = vr[3];
                    u64 pp;
                    pp = pack2(pA0[jj], pA0[jj]);
                    aA[0] = fma2(pp, v0.x, aA[0]); aA[1] = fma2(pp, v0.y, aA[1]);
                    aA[2] = fma2(pp, v1.x, aA[2]); aA[3] = fma2(pp, v1.y, aA[3]);
                    pp = pack2(pA1[jj], pA1[jj]);
                    aA[4] = fma2(pp, v2.x, aA[4]); aA[5] = fma2(pp, v2.y, aA[5]);
                    aA[6] = fma2(pp, v3.x, aA[6]); aA[7] = fma2(pp, v3.y, aA[7]);
                    pp = pack2(pB0[jj], pB0[jj]);
                    aB[0] = fma2(pp, v0.x, aB[0]); aB[1] = fma2(pp, v0.y, aB[1]);
                    aB[2] = fma2(pp, v1.x, aB[2]); aB[3] = fma2(pp, v1.y, aB[3]);
                    pp = pack2(pB1[jj], pB1[jj]);
                    aB[4] = fma2(pp, v2.x, aB[4]); aB[5] = fma2(pp, v2.y, aB[5]);
                    aB[6] = fma2(pp, v3.x, aB[6]); aB[7] = fma2(pp, v3.y, aB[7]);
                }
            }
            l0A -= (float)PADK; l1A -= (float)PADK;
            l0B -= (float)PADK; l1B -= (float)PADK;

            float i0A = __fdividef(1.f, l0A), i1A = __fdividef(1.f, l1A);
            float i0B = __fdividef(1.f, l0B), i1B = __fdividef(1.f, l1B);
            u64 z;
            z = pack2(i0A, i0A);
#pragma unroll
            for (int i = 0; i < 4; i++) oA[8 * pass + i] = mul2(aA[i], z);
            z = pack2(i1A, i1A);
#pragma unroll
            for (int i = 4; i < 8; i++) oA[8 * pass + i] = mul2(aA[i], z);
            z = pack2(i0B, i0B);
#pragma unroll
            for (int i = 0; i < 4; i++) oB[8 * pass + i] = mul2(aB[i], z);
            z = pack2(i1B, i1B);
#pragma unroll
            for (int i = 4; i < 8; i++) oB[8 * pass + i] = mul2(aB[i], z);
        }
    }
    __syncthreads();   // all warps done reading K^T/V -> V area reusable

    // ================= Phase D: Wo + residual + FFN + residual =============
    if (vA) {
        float owA[32], owB[32];
        float ssA = 0.f, ssB = 0.f;
#pragma unroll
        for (int d = 0; d < 32; d++) {
            float2 r = dot32x2(swo + d * 32, oA, oB);
            owA[d] = r.x; owB[d] = r.y;
            ssA = fmaf(r.x, r.x, ssA);
            ssB = fmaf(r.y, r.y, ssB);
        }
        float rAs = rsqrtf(ssA * 0.03125f + 1e-6f);
        float rBs = rsqrtf(ssB * 0.03125f + 1e-6f);
        u64 rsA = pack2(rAs, rAs);
        u64 rsB = pack2(rBs, rBs);

        u64 h2A[16], h2B[16];
        {
            u64 x2[16], xn[16];
            const ulonglong2* nw1 = (const ulonglong2*)(snorm + 32);
            const ulonglong2* nw2 = (const ulonglong2*)(snorm + 64);
            ld_row16(x2, gxA);
#pragma unroll
            for (int i = 0; i < 8; i++) {
                ulonglong2 n = nw1[i];
                xn[2 * i] = fma2(mul2(pack2(owA[4 * i], owA[4 * i + 1]), rsA), n.x, x2[2 * i]);
                xn[2 * i + 1] = fma2(mul2(pack2(owA[4 * i + 2], owA[4 * i + 3]), rsA), n.y, x2[2 * i + 1]);
            }
            {
                ulonglong2* xo = (ulonglong2*)(vb + tokA * ROW);
#pragma unroll
                for (int i = 0; i < 8; i++) { ulonglong2 t; t.x = xn[2 * i]; t.y = xn[2 * i + 1]; xo[i] = t; }
            }
            float rsa = rsqrtf(sumsq16(xn) * 0.03125f + 1e-6f);
            u64 rsa2 = pack2(rsa, rsa);
#pragma unroll
            for (int i = 0; i < 8; i++) {
                ulonglong2 n = nw2[i];
                h2A[2 * i] = mul2(mul2(xn[2 * i], rsa2), n.x);
                h2A[2 * i + 1] = mul2(mul2(xn[2 * i + 1], rsa2), n.y);
            }
            // token B
            ld_row16(x2, gxB);
#pragma unroll
            for (int i = 0; i < 8; i++) {
                ulonglong2 n = nw1[i];
                xn[2 * i] = fma2(mul2(pack2(owB[4 * i], owB[4 * i + 1]), rsB), n.x, x2[2 * i]);
                xn[2 * i + 1] = fma2(mul2(pack2(owB[4 * i + 2], owB[4 * i + 3]), rsB), n.y, x2[2 * i + 1]);
            }
            if (vB) {
                ulonglong2* xo = (ulonglong2*)(vb + tokB * ROW);
#pragma unroll
                for (int i = 0; i < 8; i++) { ulonglong2 t; t.x = xn[2 * i]; t.y = xn[2 * i + 1]; xo[i] = t; }
            }
            float rsb = rsqrtf(sumsq16(xn) * 0.03125f + 1e-6f);
            u64 rsb2 = pack2(rsb, rsb);
#pragma unroll
            for (int i = 0; i < 8; i++) {
                ulonglong2 n = nw2[i];
                h2B[2 * i] = mul2(mul2(xn[2 * i], rsb2), n.x);
                h2B[2 * i + 1] = mul2(mul2(xn[2 * i + 1], rsb2), n.y);
            }
        }

        // ---- FFN ----
        u64 ovA[16], ovB[16];
#pragma unroll
        for (int i = 0; i < 16; i++) { ovA[i] = 0ULL; ovB[i] = 0ULL; }

#pragma unroll 1
        for (int fg = 0; fg < 16; fg++) {
#pragma unroll
            for (int e = 0; e < 4; e++) {
                int f = fg * 4 + e;
                float2 g2 = dot32x2(swg + f * 32, h2A, h2B);
                float2 u2 = dot32x2(swu + f * 32, h2A, h2B);
                float fvA = __fdividef(g2.x, 1.f + __expf(-g2.x)) * u2.x;
                float fvB = __fdividef(g2.y, 1.f + __expf(-g2.y)) * u2.y;
                u64 fA = pack2(fvA, fvA), fB = pack2(fvB, fvB);
                const ulonglong2* wr = (const ulonglong2*)(swout + f * 32);
#pragma unroll
                for (int i = 0; i < 8; i++) {
                    ulonglong2 t = wr[i];
                    ovA[2 * i] = fma2(fA, t.x, ovA[2 * i]);
                    ovA[2 * i + 1] = fma2(fA, t.y, ovA[2 * i + 1]);
                    ovB[2 * i] = fma2(fB, t.x, ovB[2 * i]);
                    ovB[2 * i + 1] = fma2(fB, t.y, ovB[2 * i + 1]);
                }
            }
        }

        // ---- out = xn + rmsnorm(ov), reload xn from V-area, store gmem ----
        {
            const ulonglong2* nw = (const ulonglong2*)(snorm + 96);
            float rs3 = rsqrtf(sumsq16(ovA) * 0.03125f + 1e-6f);
            u64 rs32 = pack2(rs3, rs3);
            u64 xn[16];
            ld_row16(xn, vb + tokA * ROW);
            ulonglong2* go = (ulonglong2*)gxA;
#pragma unroll
            for (int i = 0; i < 8; i++) {
                ulonglong2 n = nw[i];
                ulonglong2 r;
                r.x = fma2(mul2(ovA[2 * i], rs32), n.x, xn[2 * i]);
                r.y = fma2(mul2(ovA[2 * i + 1], rs32), n.y, xn[2 * i + 1]);
                go[i] = r;
            }
            if (vB) {
                rs3 = rsqrtf(sumsq16(ovB) * 0.03125f + 1e-6f);
                rs32 = pack2(rs3, rs3);
                ld_row16(xn, vb + tokB * ROW);
                go = (ulonglong2*)gxB;
#pragma unroll
                for (int i = 0; i < 8; i++) {
                    ulonglong2 n = nw[i];
                    ulonglong2 r;
                    r.x = fma2(mul2(ovB[2 * i], rs32), n.x, xn[2 * i]);
                    r.y = fma2(mul2(ovB[2 * i + 1], rs32), n.y, xn[2 * i + 1]);
                    go[i] = r;
                }
            }
        }
    }
}

// ---------------------------------------------------------------------------
// Final: rmsnorm + extract 3 CLS tokens of last timestep.
// ---------------------------------------------------------------------------
__global__ void final_kernel(const float* __restrict__ fnorm, float* __restrict__ out) {
    int b = blockIdx.x / 3, k = blockIdx.x % 3, lane = threadIdx.x;
    float x = g_tokens[(((long)b * 128 + 127) * 67 + 64 + k) * 32 + lane];
    float ms = warp_sum(x * x) * (1.f / 32.f);
    out[(k * 16 + b) * 32 + lane] = x * rsqrtf(ms + 1e-6f) * fnorm[lane];
}

// ---------------------------------------------------------------------------
// Launch
// ---------------------------------------------------------------------------
extern "C" void kernel_launch(void* const* d_in, const int* in_sizes, int n_in,
                              void* d_out, int out_size) {
    const float* obs    = (const float*)d_in[0];
    const float* Wval   = (const float*)d_in[1];
    const float* bval   = (const float*)d_in[2];
    const float* innorm = (const float*)d_in[3];
    const float* dimemb = (const float*)d_in[4];
    const float* cls    = (const float*)d_in[5];
    const float* fnorm  = (const float*)d_in[6];
    const float* sWq   = (const float*)d_in[7];
    const float* sWk   = (const float*)d_in[8];
    const float* sWv   = (const float*)d_in[9];
    const float* sWo   = (const float*)d_in[10];
    const float* sWg   = (const float*)d_in[11];
    const float* sWu   = (const float*)d_in[12];
    const float* sWout = (const float*)d_in[13];
    const float* sN4   = (const float*)d_in[14];
    const float* sQKN  = (const float*)d_in[15];
    const float* tWq   = (const float*)d_in[16];
    const float* tWk   = (const float*)d_in[17];
    const float* tWv   = (const float*)d_in[18];
    const float* tWo   = (const float*)d_in[19];
    const float* tWg   = (const float*)d_in[20];
    const float* tWu   = (const float*)d_in[21];
    const float* tWout = (const float*)d_in[22];
    const float* tN4   = (const float*)d_in[23];
    const float* tQKN  = (const float*)d_in[24];

    // smem floats: NSEQ*(32*SP4 + SP4*36) + 10240 + 144 + 192
    const int SZ_S = (3 * (32 * 68 + 68 * 36) + 10240 + 144 + 192) * 4;     // 97840
    const int SZ_T = (4 * (32 * 128 + 128 * 36) + 10240 + 144 + 192) * 4;   // 181568

    cudaFuncSetAttribute(attn_tpl<67, 3, false, true>, cudaFuncAttributeMaxDynamicSharedMemorySize, SZ_S);
    cudaFuncSetAttribute(attn_tpl<67, 3, false, false>, cudaFuncAttributeMaxDynamicSharedMemorySize, SZ_S);
    cudaFuncSetAttribute(attn_tpl<128, 4, true, false>, cudaFuncAttributeMaxDynamicSharedMemorySize, SZ_T);

    const int GRID_S = (2048 + 2) / 3;   // 683
    const int GRID_T = 1072 / 4;         // 268

    for (int layer = 0; layer < 3; layer++) {
        if (layer == 0) {
            attn_tpl<67, 3, false, true><<<GRID_S, 128, SZ_S>>>(
                sWq, sWk, sWv, sWo, sWg, sWu, sWout, sN4, sQKN, 2048,
                obs, Wval, bval, innorm, dimemb, cls);
        } else {
            attn_tpl<67, 3, false, false><<<GRID_S, 128, SZ_S>>>(
                sWq + layer * 1024, sWk + layer * 1024, sWv + layer * 1024, sWo + layer * 1024,
                sWg + layer * 2048, sWu + layer * 2048, sWout + layer * 2048,
                sN4 + layer * 128, sQKN + layer * 16, 2048,
                nullptr, nullptr, nullptr, nullptr, nullptr, nullptr);
        }
        if (layer < 2) {
            attn_tpl<128, 4, true, false><<<GRID_T, 256, SZ_T>>>(
                tWq + layer * 1024, tWk + layer * 1024, tWv + layer * 1024, tWo + layer * 1024,
                tWg + layer * 2048, tWu + layer * 2048, tWout + layer * 2048,
                tN4 + layer * 128, tQKN + layer * 16, 1072,
                nullptr, nullptr, nullptr, nullptr, nullptr, nullptr);
        }
    }

    final_kernel<<<48, 32>>>(fnorm, (float*)d_out);
}

// round 17
// speedup vs baseline: 1.0637x; 1.0116x over previous
#include <cuda_runtime.h>
#include <math.h>

#define FULL 0xffffffffu
typedef unsigned long long u64;

// Scratch token buffer: (B=16, T=128, slots=67, EMBED=32) fp32
__device__ float g_tokens[16 * 128 * 67 * 32];

__device__ __forceinline__ float warp_sum(float v) {
    v += __shfl_xor_sync(FULL, v, 16);
    v += __shfl_xor_sync(FULL, v, 8);
    v += __shfl_xor_sync(FULL, v, 4);
    v += __shfl_xor_sync(FULL, v, 2);
    v += __shfl_xor_sync(FULL, v, 1);
    return v;
}

// ---- packed f32x2 helpers ----
__device__ __forceinline__ u64 fma2(u64 a, u64 b, u64 c) {
    u64 d; asm("fma.rn.f32x2 %0, %1, %2, %3;" : "=l"(d) : "l"(a), "l"(b), "l"(c)); return d;
}
__device__ __forceinline__ u64 mul2(u64 a, u64 b) {
    u64 d; asm("mul.rn.f32x2 %0, %1, %2;" : "=l"(d) : "l"(a), "l"(b)); return d;
}
__device__ __forceinline__ u64 add2(u64 a, u64 b) {
    u64 d; asm("add.rn.f32x2 %0, %1, %2;" : "=l"(d) : "l"(a), "l"(b)); return d;
}
__device__ __forceinline__ u64 pack2(float lo, float hi) {
    u64 d; asm("mov.b64 %0, {%1, %2};" : "=l"(d) : "f"(lo), "f"(hi)); return d;
}
__device__ __forceinline__ float hsum2(u64 v) {
    float lo, hi; asm("mov.b64 {%0, %1}, %2;" : "=f"(lo), "=f"(hi) : "l"(v)); return lo + hi;
}
__device__ __forceinline__ void unpk(u64 v, float& a, float& b) {
    asm("mov.b64 {%0, %1}, %2;" : "=f"(a), "=f"(b) : "l"(v));
}
// base-2 exp, scores pre-scaled by log2(e)
__device__ __forceinline__ float ex2f(float x) {
    float y; asm("ex2.approx.f32 %0, %1;" : "=f"(y) : "f"(x)); return y;
}

__device__ __forceinline__ void ld_row16(u64* r, const float* p) {
    const ulonglong2* q = (const ulonglong2*)p;
#pragma unroll
    for (int i = 0; i < 8; i++) { ulonglong2 t = q[i]; r[2 * i] = t.x; r[2 * i + 1] = t.y; }
}

// one weight row read, TWO dots (token pair)
__device__ __forceinline__ float2 dot32x2(const float* wrow, const u64* a, const u64* b) {
    const ulonglong2* w = (const ulonglong2*)wrow;
    ulonglong2 t0 = w[0], t1 = w[1];
    u64 a0 = mul2(a[0], t0.x), b0 = mul2(b[0], t0.x);
    a0 = fma2(a[1], t0.y, a0); b0 = fma2(b[1], t0.y, b0);
    u64 a1 = mul2(a[2], t1.x), b1 = mul2(b[2], t1.x);
    a1 = fma2(a[3], t1.y, a1); b1 = fma2(b[3], t1.y, b1);
#pragma unroll
    for (int i = 2; i < 8; i += 2) {
        ulonglong2 u0 = w[i], u1 = w[i + 1];
        a0 = fma2(a[2 * i], u0.x, a0);     b0 = fma2(b[2 * i], u0.x, b0);
        a0 = fma2(a[2 * i + 1], u0.y, a0); b0 = fma2(b[2 * i + 1], u0.y, b0);
        a1 = fma2(a[2 * i + 2], u1.x, a1); b1 = fma2(b[2 * i + 2], u1.x, b1);
        a1 = fma2(a[2 * i + 3], u1.y, a1); b1 = fma2(b[2 * i + 3], u1.y, b1);
    }
    return make_float2(hsum2(add2(a0, a1)), hsum2(add2(b0, b1)));
}

__device__ __forceinline__ float sumsq16(const u64* v) {
    u64 a0 = mul2(v[0], v[0]);
    u64 a1 = mul2(v[1], v[1]);
#pragma unroll
    for (int i = 2; i < 16; i += 2) {
        a0 = fma2(v[i], v[i], a0);
        a1 = fma2(v[i + 1], v[i + 1], a1);
    }
    return hsum2(add2(a0, a1));
}

// ---------------------------------------------------------------------------
// Monolithic fused block (R16 compute, PDL added). Transposed-K packed-score
// attention; 2 tokens/lane; two head-split passes; base-2 softmax.
// EMB0: layer-0 spatial computes token embedding + input rmsnorm in-kernel.
// PDL: weight staging runs before cudaGridDependencySynchronize() so it
// overlaps the previous kernel's tail; trigger fires after the last store.
// ---------------------------------------------------------------------------
template <int S, int NSEQ, bool TEMPORAL, bool EMB0>
__global__ void __launch_bounds__(32 * ((((S + 1) / 2) * NSEQ + 31) / 32))
attn_tpl(const float* __restrict__ Wq, const float* __restrict__ Wk,
         const float* __restrict__ Wv, const float* __restrict__ Wo,
         const float* __restrict__ Wg, const float* __restrict__ Wu,
         const float* __restrict__ Wout, const float* __restrict__ norm4,
         const float* __restrict__ qkn, int nseq_total,
         const float* __restrict__ eobs, const float* __restrict__ eWval,
         const float* __restrict__ ebval, const float* __restrict__ einnorm,
         const float* __restrict__ edimemb, const float* __restrict__ ecls) {
    constexpr int HS = (S + 1) / 2;
    constexpr int BLK = 32 * ((HS * NSEQ + 31) / 32);
    constexpr int SP4 = ((S + 3) / 4) * 4;       // keys padded to mult of 4
    constexpr int PADK = SP4 - S;
    constexpr int ROW = 36;                      // V row stride
    constexpr int KTSZ = 32 * SP4;               // K^T area per seq
    constexpr int SEQSTR = KTSZ + SP4 * ROW;
    constexpr int DATSZ = NSEQ * SEQSTR;

    extern __shared__ float sm[];
    float* skv   = sm;                 // DATSZ
    float* swq   = skv + DATSZ;        // 1024
    float* swk   = swq + 1024;
    float* swv   = swk + 1024;
    float* swo   = swv + 1024;
    float* swg   = swo + 1024;         // 2048
    float* swu   = swg + 2048;         // 2048
    float* swout = swu + 2048;         // 2048 transposed [f][d]
    float* snorm = swout + 2048;       // 128
    float* sqkn  = snorm + 128;        // 16
    float* semb  = sqkn + 16;          // 192 (Wval,bval,innorm,cls)

    const int tid = threadIdx.x;
    int gseq0 = blockIdx.x * NSEQ;

    // ---- stage weights (independent of previous kernel's output) ----
    for (int i = tid; i < 256; i += BLK) {
        ((float4*)swq)[i] = ((const float4*)Wq)[i];
        ((float4*)swk)[i] = ((const float4*)Wk)[i];
        ((float4*)swv)[i] = ((const float4*)Wv)[i];
        ((float4*)swo)[i] = ((const float4*)Wo)[i];
    }
    for (int i = tid; i < 512; i += BLK) {
        ((float4*)swg)[i] = ((const float4*)Wg)[i];
        ((float4*)swu)[i] = ((const float4*)Wu)[i];
    }
    for (int i = tid; i < 2048; i += BLK) {   // transpose Wout -> [f][d]
        int f = i >> 5, d = i & 31;
        swout[i] = Wout[d * 64 + f];
    }
    if (tid < 128) snorm[tid] = norm4[tid];
    if (tid < 16) sqkn[tid] = qkn[tid];
    if (EMB0) {
        if (tid < 32) {
            semb[tid] = eWval[tid];
            semb[32 + tid] = ebval[tid];
            semb[64 + tid] = einnorm[tid];
        }
        if (tid < 96) semb[96 + tid] = ecls[tid];
    }

    // ---- zero pad keys: K^T columns S..SP4-1 (32 dims) + V rows S..SP4-1 --
    if (PADK > 0) {
        constexpr int PER = (32 + ROW) * PADK;
        for (int i = tid; i < NSEQ * PER; i += BLK) {
            int sq = i / PER;
            int r = i - sq * PER;
            float* sb = skv + sq * SEQSTR;
            if (r < 32 * PADK) {
                int d = r / PADK, pc = r - d * PADK;
                sb[d * SP4 + S + pc] = 0.f;
            } else {
                int rr = r - 32 * PADK;
                sb[KTSZ + (S + rr / ROW) * ROW + rr % ROW] = 0.f;
            }
        }
    }

    // Wait for the previous kernel's g_tokens writes to be visible.
    cudaGridDependencySynchronize();

    // ---- token-pair assignment ----
    int seq = tid / HS;
    int l = tid - seq * HS;
    bool seqok = (seq < NSEQ) && (gseq0 + seq < nseq_total);
    int seqc = seqok ? seq : 0;
    bool vA = seqok;
    bool vB = seqok && (l + HS < S);
    int tokA = l;
    int tokB = vB ? (l + HS) : (S - 1);

    float* kT = skv + seqc * SEQSTR;
    float* vb = kT + KTSZ;

    float *gxA, *gxB;
    {
        int gs = gseq0 + seqc;
        if (TEMPORAL) {
            int b = gs / 67, sl = gs - b * 67;
            gxA = g_tokens + ((long)(b * 128 + tokA) * 67 + sl) * 32;
            gxB = g_tokens + ((long)(b * 128 + tokB) * 67 + sl) * 32;
        } else {
            gxA = g_tokens + ((long)gs * 67 + tokA) * 32;
            gxB = g_tokens + ((long)gs * 67 + tokB) * 32;
        }
    }

    __syncthreads();

    u64 qA[16], qB[16];

    // ================= Phase B: norm + QKV (+qk-norm, rope) ================
    if (vA) {
        float qknQ[8], qknK[8];
#pragma unroll
        for (int e = 0; e < 8; e++) {
            qknQ[e] = sqkn[e] * (0.35355339059327373f * 1.4426950408889634f);
            qknK[e] = sqkn[8 + e];
        }
        float csA[4], snA[4], csB[4], snB[4];
        if (TEMPORAL) {
            const float th[4] = {1.f, 0.1f, 0.01f, 0.001f};
#pragma unroll
            for (int j = 0; j < 4; j++) {
                __sincosf((float)tokA * th[j], &snA[j], &csA[j]);
                __sincosf((float)tokB * th[j], &snB[j], &csB[j]);
            }
        }

        u64 hA[16], hB[16];
        {
            int gs = gseq0 + seqc;
            u64 x2[16];
#pragma unroll
            for (int which = 0; which < 2; which++) {
                int tok = which ? tokB : tokA;
                float* gx = which ? gxB : gxA;
                if (EMB0) {
                    float raw[32];
                    if (tok < 64) {
                        float obsv = eobs[gs * 64 + tok];
                        const float4* de = (const float4*)(edimemb + tok * 32);
#pragma unroll
                        for (int c = 0; c < 8; c++) {
                            float4 dv = de[c];
                            raw[4 * c]     = fmaf(obsv, semb[4 * c],     semb[32 + 4 * c])     + dv.x;
                            raw[4 * c + 1] = fmaf(obsv, semb[4 * c + 1], semb[32 + 4 * c + 1]) + dv.y;
                            raw[4 * c + 2] = fmaf(obsv, semb[4 * c + 2], semb[32 + 4 * c + 2]) + dv.z;
                            raw[4 * c + 3] = fmaf(obsv, semb[4 * c + 3], semb[32 + 4 * c + 3]) + dv.w;
                        }
                    } else {
#pragma unroll
                        for (int d = 0; d < 32; d++) raw[d] = semb[96 + (tok - 64) * 32 + d];
                    }
                    float ss = 0.f;
#pragma unroll
                    for (int d = 0; d < 32; d++) ss = fmaf(raw[d], raw[d], ss);
                    float rsx = rsqrtf(ss * 0.03125f + 1e-6f);
                    float4* go = (float4*)gx;
#pragma unroll
                    for (int c = 0; c < 8; c++) {
                        float x0 = raw[4 * c] * rsx * semb[64 + 4 * c];
                        float x1 = raw[4 * c + 1] * rsx * semb[64 + 4 * c + 1];
                        float x2v = raw[4 * c + 2] * rsx * semb[64 + 4 * c + 2];
                        float x3 = raw[4 * c + 3] * rsx * semb[64 + 4 * c + 3];
                        go[c] = make_float4(x0, x1, x2v, x3);
                        x2[2 * c] = pack2(x0, x1);
                        x2[2 * c + 1] = pack2(x2v, x3);
                    }
                } else {
                    ld_row16(x2, gx);
                }
                float rs = rsqrtf(sumsq16(x2) * 0.03125f + 1e-6f);
                u64 rs2 = pack2(rs, rs);
                const ulonglong2* nw = (const ulonglong2*)snorm;
                u64* h = which ? hB : hA;
#pragma unroll
                for (int i = 0; i < 8; i++) {
                    ulonglong2 n = nw[i];
                    h[2 * i] = mul2(mul2(x2[2 * i], rs2), n.x);
                    h[2 * i + 1] = mul2(mul2(x2[2 * i + 1], rs2), n.y);
                }
            }
        }

        // ---- K heads: store into K^T (keys contiguous) ----
#pragma unroll 1
        for (int hh = 0; hh < 4; hh++) {
            float aA[8], aB[8];
#pragma unroll
            for (int e = 0; e < 8; e++) {
                float2 d = dot32x2(swk + (hh * 8 + e) * 32, hA, hB);
                aA[e] = d.x; aB[e] = d.y;
            }
            float msA = 0, msB = 0;
#pragma unroll
            for (int e = 0; e < 8; e++) { msA = fmaf(aA[e], aA[e], msA); msB = fmaf(aB[e], aB[e], msB); }
            float scA = rsqrtf(msA * 0.125f + 1e-6f);
            float scB = rsqrtf(msB * 0.125f + 1e-6f);
#pragma unroll
            for (int e = 0; e < 8; e++) { aA[e] *= scA * qknK[e]; aB[e] *= scB * qknK[e]; }
            if (TEMPORAL) {
#pragma unroll
                for (int e = 0; e < 4; e++) {
                    float t0 = aA[e], t1 = aA[e + 4];
                    aA[e] = t0 * csA[e] - t1 * snA[e];
                    aA[e + 4] = fmaf(t0, snA[e], t1 * csA[e]);
                    t0 = aB[e]; t1 = aB[e + 4];
                    aB[e] = t0 * csB[e] - t1 * snB[e];
                    aB[e + 4] = fmaf(t0, snB[e], t1 * csB[e]);
                }
            }
#pragma unroll
            for (int e = 0; e < 8; e++) {
                kT[(hh * 8 + e) * SP4 + tokA] = aA[e];
                if (vB) kT[(hh * 8 + e) * SP4 + tokB] = aB[e];
            }
        }

        // ---- V heads (row-major) ----
#pragma unroll 1
        for (int hh = 0; hh < 4; hh++) {
            float aA[8], aB[8];
#pragma unroll
            for (int e = 0; e < 8; e++) {
                float2 d = dot32x2(swv + (hh * 8 + e) * 32, hA, hB);
                aA[e] = d.x; aB[e] = d.y;
            }
            float* dA = vb + tokA * ROW + hh * 8;
            *(float4*)dA = make_float4(aA[0], aA[1], aA[2], aA[3]);
            *(float4*)(dA + 4) = make_float4(aA[4], aA[5], aA[6], aA[7]);
            if (vB) {
                float* dB = vb + tokB * ROW + hh * 8;
                *(float4*)dB = make_float4(aB[0], aB[1], aB[2], aB[3]);
                *(float4*)(dB + 4) = make_float4(aB[4], aB[5], aB[6], aB[7]);
            }
        }

        // ---- Q heads ----
#pragma unroll
        for (int hh = 0; hh < 4; hh++) {
            float aA[8], aB[8];
#pragma unroll
            for (int e = 0; e < 8; e++) {
                float2 d = dot32x2(swq + (hh * 8 + e) * 32, hA, hB);
                aA[e] = d.x; aB[e] = d.y;
            }
            float msA = 0, msB = 0;
#pragma unroll
            for (int e = 0; e < 8; e++) { msA = fmaf(aA[e], aA[e], msA); msB = fmaf(aB[e], aB[e], msB); }
            float scA = rsqrtf(msA * 0.125f + 1e-6f);
            float scB = rsqrtf(msB * 0.125f + 1e-6f);
#pragma unroll
            for (int e = 0; e < 8; e++) { aA[e] *= scA * qknQ[e]; aB[e] *= scB * qknQ[e]; }
            if (TEMPORAL) {
#pragma unroll
                for (int e = 0; e < 4; e++) {
                    float t0 = aA[e], t1 = aA[e + 4];
                    aA[e] = t0 * csA[e] - t1 * snA[e];
                    aA[e + 4] = fmaf(t0, snA[e], t1 * csA[e]);
                    t0 = aB[e]; t1 = aB[e + 4];
                    aB[e] = t0 * csB[e] - t1 * snB[e];
                    aB[e + 4] = fmaf(t0, snB[e], t1 * csB[e]);
                }
            }
#pragma unroll
            for (int j = 0; j < 4; j++) {
                qA[4 * hh + j] = pack2(aA[2 * j], aA[2 * j + 1]);
                qB[4 * hh + j] = pack2(aB[2 * j], aB[2 * j + 1]);
            }
        }
    }
    __syncthreads();

    // ====== Phase C: packed-score attention, two head-split passes =========
    u64 oA[16], oB[16];
    if (vA) {
#pragma unroll
        for (int pass = 0; pass < 2; pass++) {
            u64 qdA[16], qdB[16];
#pragma unroll
            for (int i = 0; i < 8; i++) {
                float lo, hi;
                unpk(qA[8 * pass + i], lo, hi);
                qdA[2 * i] = pack2(lo, lo); qdA[2 * i + 1] = pack2(hi, hi);
                unpk(qB[8 * pass + i], lo, hi);
                qdB[2 * i] = pack2(lo, lo); qdB[2 * i + 1] = pack2(hi, hi);
            }
            u64 aA[8], aB[8];
#pragma unroll
            for (int i = 0; i < 8; i++) { aA[i] = 0ULL; aB[i] = 0ULL; }
            float l0A = 0.f, l1A = 0.f, l0B = 0.f, l1B = 0.f;
            const float* kTp = kT + (16 * pass) * SP4;
            const float* vp = vb + 16 * pass;

#pragma unroll 1
            for (int jb = 0; jb < SP4; jb += 4) {
                u64 sA0a = 0, sA0b = 0, sA1a = 0, sA1b = 0;
                u64 sB0a = 0, sB0b = 0, sB1a = 0, sB1b = 0;
#pragma unroll
                for (int d = 0; d < 8; d++) {
                    ulonglong2 t0 = *(const ulonglong2*)(kTp + d * SP4 + jb);
                    ulonglong2 t1 = *(const ulonglong2*)(kTp + (d + 8) * SP4 + jb);
                    sA0a = fma2(qdA[d], t0.x, sA0a); sA0b = fma2(qdA[d], t0.y, sA0b);
                    sB0a = fma2(qdB[d], t0.x, sB0a); sB0b = fma2(qdB[d], t0.y, sB0b);
                    sA1a = fma2(qdA[8 + d], t1.x, sA1a); sA1b = fma2(qdA[8 + d], t1.y, sA1b);
                    sB1a = fma2(qdB[8 + d], t1.x, sB1a); sB1b = fma2(qdB[8 + d], t1.y, sB1b);
                }
                float pA0[4], pA1[4], pB0[4], pB1[4];
                unpk(sA0a, pA0[0], pA0[1]); unpk(sA0b, pA0[2], pA0[3]);
                unpk(sA1a, pA1[0], pA1[1]); unpk(sA1b, pA1[2], pA1[3]);
                unpk(sB0a, pB0[0], pB0[1]); unpk(sB0b, pB0[2], pB0[3]);
                unpk(sB1a, pB1[0], pB1[1]); unpk(sB1b, pB1[2], pB1[3]);
#pragma unroll
                for (int jj = 0; jj < 4; jj++) {
                    pA0[jj] = ex2f(pA0[jj]); l0A += pA0[jj];
                    pA1[jj] = ex2f(pA1[jj]); l1A += pA1[jj];
                    pB0[jj] = ex2f(pB0[jj]); l0B += pB0[jj];
                    pB1[jj] = ex2f(pB1[jj]); l1B += pB1[jj];
                }
#pragma unroll
                for (int jj = 0; jj < 4; jj++) {
                    const ulonglong2* vr = (const ulonglong2*)(vp + (jb + jj) * ROW);
                    ulonglong2 v0 = vr[0], v1 = vr[1], v2 = vr[2], v3 = vr[3];
                    u64 pp;
                    pp = pack2(pA0[jj], pA0[jj]);
                    aA[0] = fma2(pp, v0.x, aA[0]); aA[1] = fma2(pp, v0.y, aA[1]);
                    aA[2] = fma2(pp, v1.x, aA[2]); aA[3] = fma2(pp, v1.y, aA[3]);
                    pp = pack2(pA1[jj], pA1[jj]);
                    aA[4] = fma2(pp, v2.x, aA[4]); aA[5] = fma2(pp, v2.y, aA[5]);
                    aA[6] = fma2(pp, v3.x, aA[6]); aA[7] = fma2(pp, v3.y, aA[7]);
                    pp = pack2(pB0[jj], pB0[jj]);
                    aB[0] = fma2(pp, v0.x, aB[0]); aB[1] = fma2(pp, v0.y, aB[1]);
                    aB[2] = fma2(pp, v1.x, aB[2]); aB[3] = fma2(pp, v1.y, aB[3]);
                    pp = pack2(pB1[jj], pB1[jj]);
                    aB[4] = fma2(pp, v2.x, aB[4]); aB[5] = fma2(pp, v2.y, aB[5]);
                    aB[6] = fma2(pp, v3.x, aB[6]); aB[7] = fma2(pp, v3.y, aB[7]);
                }
            }
            l0A -= (float)PADK; l1A -= (float)PADK;
            l0B -= (float)PADK; l1B -= (float)PADK;

            float i0A = __fdividef(1.f, l0A), i1A = __fdividef(1.f, l1A);
            float i0B = __fdividef(1.f, l0B), i1B = __fdividef(1.f, l1B);
            u64 z;
            z = pack2(i0A, i0A);
#pragma unroll
            for (int i = 0; i < 4; i++) oA[8 * pass + i] = mul2(aA[i], z);
            z = pack2(i1A, i1A);
#pragma unroll
            for (int i = 4; i < 8; i++) oA[8 * pass + i] = mul2(aA[i], z);
            z = pack2(i0B, i0B);
#pragma unroll
            for (int i = 0; i < 4; i++) oB[8 * pass + i] = mul2(aB[i], z);
            z = pack2(i1B, i1B);
#pragma unroll
            for (int i = 4; i < 8; i++) oB[8 * pass + i] = mul2(aB[i], z);
        }
    }
    __syncthreads();   // all warps done reading K^T/V -> V area reusable

    // ================= Phase D: Wo + residual + FFN + residual =============
    if (vA) {
        float owA[32], owB[32];
        float ssA = 0.f, ssB = 0.f;
#pragma unroll
        for (int d = 0; d < 32; d++) {
            float2 r = dot32x2(swo + d * 32, oA, oB);
            owA[d] = r.x; owB[d] = r.y;
            ssA = fmaf(r.x, r.x, ssA);
            ssB = fmaf(r.y, r.y, ssB);
        }
        float rAs = rsqrtf(ssA * 0.03125f + 1e-6f);
        float rBs = rsqrtf(ssB * 0.03125f + 1e-6f);
        u64 rsA = pack2(rAs, rAs);
        u64 rsB = pack2(rBs, rBs);

        u64 h2A[16], h2B[16];
        {
            u64 x2[16], xn[16];
            const ulonglong2* nw1 = (const ulonglong2*)(snorm + 32);
            const ulonglong2* nw2 = (const ulonglong2*)(snorm + 64);
            ld_row16(x2, gxA);
#pragma unroll
            for (int i = 0; i < 8; i++) {
                ulonglong2 n = nw1[i];
                xn[2 * i] = fma2(mul2(pack2(owA[4 * i], owA[4 * i + 1]), rsA), n.x, x2[2 * i]);
                xn[2 * i + 1] = fma2(mul2(pack2(owA[4 * i + 2], owA[4 * i + 3]), rsA), n.y, x2[2 * i + 1]);
            }
            {
                ulonglong2* xo = (ulonglong2*)(vb + tokA * ROW);
#pragma unroll
                for (int i = 0; i < 8; i++) { ulonglong2 t; t.x = xn[2 * i]; t.y = xn[2 * i + 1]; xo[i] = t; }
            }
            float rsa = rsqrtf(sumsq16(xn) * 0.03125f + 1e-6f);
            u64 rsa2 = pack2(rsa, rsa);
#pragma unroll
            for (int i = 0; i < 8; i++) {
                ulonglong2 n = nw2[i];
                h2A[2 * i] = mul2(mul2(xn[2 * i], rsa2), n.x);
                h2A[2 * i + 1] = mul2(mul2(xn[2 * i + 1], rsa2), n.y);
            }
            // token B
            ld_row16(x2, gxB);
#pragma unroll
            for (int i = 0; i < 8; i++) {
                ulonglong2 n = nw1[i];
                xn[2 * i] = fma2(mul2(pack2(owB[4 * i], owB[4 * i + 1]), rsB), n.x, x2[2 * i]);
                xn[2 * i + 1] = fma2(mul2(pack2(owB[4 * i + 2], owB[4 * i + 3]), rsB), n.y, x2[2 * i + 1]);
            }
            if (vB) {
                ulonglong2* xo = (ulonglong2*)(vb + tokB * ROW);
#pragma unroll
                for (int i = 0; i < 8; i++) { ulonglong2 t; t.x = xn[2 * i]; t.y = xn[2 * i + 1]; xo[i] = t; }
            }
            float rsb = rsqrtf(sumsq16(xn) * 0.03125f + 1e-6f);
            u64 rsb2 = pack2(rsb, rsb);
#pragma unroll
            for (int i = 0; i < 8; i++) {
                ulonglong2 n = nw2[i];
                h2B[2 * i] = mul2(mul2(xn[2 * i], rsb2), n.x);
                h2B[2 * i + 1] = mul2(mul2(xn[2 * i + 1], rsb2), n.y);
            }
        }

        // ---- FFN ----
        u64 ovA[16], ovB[16];
#pragma unroll
        for (int i = 0; i < 16; i++) { ovA[i] = 0ULL; ovB[i] = 0ULL; }

#pragma unroll 1
        for (int fg = 0; fg < 16; fg++) {
#pragma unroll
            for (int e = 0; e < 4; e++) {
                int f = fg * 4 + e;
                float2 g2 = dot32x2(swg + f * 32, h2A, h2B);
                float2 u2 = dot32x2(swu + f * 32, h2A, h2B);
                float fvA = __fdividef(g2.x, 1.f + __expf(-g2.x)) * u2.x;
                float fvB = __fdividef(g2.y, 1.f + __expf(-g2.y)) * u2.y;
                u64 fA = pack2(fvA, fvA), fB = pack2(fvB, fvB);
                const ulonglong2* wr = (const ulonglong2*)(swout + f * 32);
#pragma unroll
                for (int i = 0; i < 8; i++) {
                    ulonglong2 t = wr[i];
                    ovA[2 * i] = fma2(fA, t.x, ovA[2 * i]);
                    ovA[2 * i + 1] = fma2(fA, t.y, ovA[2 * i + 1]);
                    ovB[2 * i] = fma2(fB, t.x, ovB[2 * i]);
                    ovB[2 * i + 1] = fma2(fB, t.y, ovB[2 * i + 1]);
                }
            }
        }

        // ---- out = xn + rmsnorm(ov), reload xn from V-area, store gmem ----
        {
            const ulonglong2* nw = (const ulonglong2*)(snorm + 96);
            float rs3 = rsqrtf(sumsq16(ovA) * 0.03125f + 1e-6f);
            u64 rs32 = pack2(rs3, rs3);
            u64 xn[16];
            ld_row16(xn, vb + tokA * ROW);
            ulonglong2* go = (ulonglong2*)gxA;
#pragma unroll
            for (int i = 0; i < 8; i++) {
                ulonglong2 n = nw[i];
                ulonglong2 r;
                r.x = fma2(mul2(ovA[2 * i], rs32), n.x, xn[2 * i]);
                r.y = fma2(mul2(ovA[2 * i + 1], rs32), n.y, xn[2 * i + 1]);
                go[i] = r;
            }
            if (vB) {
                rs3 = rsqrtf(sumsq16(ovB) * 0.03125f + 1e-6f);
                rs32 = pack2(rs3, rs3);
                ld_row16(xn, vb + tokB * ROW);
                go = (ulonglong2*)gxB;
#pragma unroll
                for (int i = 0; i < 8; i++) {
                    ulonglong2 n = nw[i];
                    ulonglong2 r;
                    r.x = fma2(mul2(ovB[2 * i], rs32), n.x, xn[2 * i]);
                    r.y = fma2(mul2(ovB[2 * i + 1], rs32), n.y, xn[2 * i + 1]);
                    go[i] = r;
                }
            }
        }
    }

    // allow the next kernel to begin launching
    cudaTriggerProgrammaticLaunchCompletion();
}

// ---------------------------------------------------------------------------
// Final: rmsnorm + extract 3 CLS tokens of last timestep.
// ---------------------------------------------------------------------------
__global__ void final_kernel(const float* __restrict__ fnorm, float* __restrict__ out) {
    cudaGridDependencySynchronize();
    int b = blockIdx.x / 3, k = blockIdx.x % 3, lane = threadIdx.x;
    float x = g_tokens[(((long)b * 128 + 127) * 67 + 64 + k) * 32 + lane];
    float ms = warp_sum(x * x) * (1.f / 32.f);
    out[(k * 16 + b) * 32 + lane] = x * rsqrtf(ms + 1e-6f) * fnorm[lane];
}

// ---------------------------------------------------------------------------
// Launch (all kernels with PDL stream serialization)
// ---------------------------------------------------------------------------
template <typename F, typename... Args>
static inline void launch_pdl(F* func, int grid, int block, int smem, Args... args) {
    cudaLaunchConfig_t cfg = {};
    cfg.gridDim = dim3(grid, 1, 1);
    cfg.blockDim = dim3(block, 1, 1);
    cfg.dynamicSmemBytes = (size_t)smem;
    cfg.stream = 0;
    cudaLaunchAttribute attr[1];
    attr[0].id = cudaLaunchAttributeProgrammaticStreamSerialization;
    attr[0].val.programmaticStreamSerializationAllowed = 1;
    cfg.attrs = attr;
    cfg.numAttrs = 1;
    cudaLaunchKernelEx(&cfg, func, args...);
}

extern "C" void kernel_launch(void* const* d_in, const int* in_sizes, int n_in,
                              void* d_out, int out_size) {
    const float* obs    = (const float*)d_in[0];
    const float* Wval   = (const float*)d_in[1];
    const float* bval   = (const float*)d_in[2];
    const float* innorm = (const float*)d_in[3];
    const float* dimemb = (const float*)d_in[4];
    const float* cls    = (const float*)d_in[5];
    const float* fnorm  = (const float*)d_in[6];
    const float* sWq   = (const float*)d_in[7];
    const float* sWk   = (const float*)d_in[8];
    const float* sWv   = (const float*)d_in[9];
    const float* sWo   = (const float*)d_in[10];
    const float* sWg   = (const float*)d_in[11];
    const float* sWu   = (const float*)d_in[12];
    const float* sWout = (const float*)d_in[13];
    const float* sN4   = (const float*)d_in[14];
    const float* sQKN  = (const float*)d_in[15];
    const float* tWq   = (const float*)d_in[16];
    const float* tWk   = (const float*)d_in[17];
    const float* tWv   = (const float*)d_in[18];
    const float* tWo   = (const float*)d_in[19];
    const float* tWg   = (const float*)d_in[20];
    const float* tWu   = (const float*)d_in[21];
    const float* tWout = (const float*)d_in[22];
    const float* tN4   = (const float*)d_in[23];
    const float* tQKN  = (const float*)d_in[24];

    // smem floats: NSEQ*(32*SP4 + SP4*36) + 10240 + 144 + 192
    const int SZ_S = (3 * (32 * 68 + 68 * 36) + 10240 + 144 + 192) * 4;     // 97840
    const int SZ_T = (4 * (32 * 128 + 128 * 36) + 10240 + 144 + 192) * 4;   // 181568

    cudaFuncSetAttribute(attn_tpl<67, 3, false, true>, cudaFuncAttributeMaxDynamicSharedMemorySize, SZ_S);
    cudaFuncSetAttribute(attn_tpl<67, 3, false, false>, cudaFuncAttributeMaxDynamicSharedMemorySize, SZ_S);
    cudaFuncSetAttribute(attn_tpl<128, 4, true, false>, cudaFuncAttributeMaxDynamicSharedMemorySize, SZ_T);

    const int GRID_S = (2048 + 2) / 3;   // 683
    const int GRID_T = 1072 / 4;         // 268

    for (int layer = 0; layer < 3; layer++) {
        if (layer == 0) {
            launch_pdl(attn_tpl<67, 3, false, true>, GRID_S, 128, SZ_S,
                       sWq, sWk, sWv, sWo, sWg, sWu, sWout, sN4, sQKN, 2048,
                       obs, Wval, bval, innorm, dimemb, cls);
        } else {
            launch_pdl(attn_tpl<67, 3, false, false>, GRID_S, 128, SZ_S,
                       sWq + layer * 1024, sWk + layer * 1024, sWv + layer * 1024, sWo + layer * 1024,
                       sWg + layer * 2048, sWu + layer * 2048, sWout + layer * 2048,
                       sN4 + layer * 128, sQKN + layer * 16, 2048,
                       (const float*)nullptr, (const float*)nullptr, (const float*)nullptr,
                       (const float*)nullptr, (const float*)nullptr, (const float*)nullptr);
        }
        if (layer < 2) {
            launch_pdl(attn_tpl<128, 4, true, false>, GRID_T, 256, SZ_T,
                       tWq + layer * 1024, tWk + layer * 1024, tWv + layer * 1024, tWo + layer * 1024,
                       tWg + layer * 2048, tWu + layer * 2048, tWout + layer * 2048,
                       tN4 + layer * 128, tQKN + layer * 16, 1072,
                       (const float*)nullptr, (const float*)nullptr, (const float*)nullptr,
                       (const float*)nullptr, (const float*)nullptr, (const float*)nullptr);
        }
    }

    launch_pdl(final_kernel, 48, 32, 0, fnorm, (float*)d_out);
}